// round 3
// baseline (speedup 1.0000x reference)
#include <cuda_runtime.h>
#include <math.h>

#define Bn 32768
#define Kn 32
#define Dn 256
#define Hn 8
#define DKn 32
#define FFn 1024

// Scratch (static device globals; allocation-free per harness rules)
__device__ float g_q[Bn * Dn];            // 33.5 MB  Q projection
__device__ float g_u[Bn * Hn * Dn];       // 268 MB   folded-K query vectors
__device__ float g_y[Bn * Hn * Dn];       // 268 MB   attn-weighted neighbor sums
__device__ float g_xres[Bn * Dn];         // 33.5 MB  x + attn_out @ W_o
__device__ float g_hn[Bn * Dn];           // 33.5 MB  LN2(xres)
__device__ float g_ff[Bn * FFn];          // 134 MB   gelu(hn@W1+b1)

// ---------------------------------------------------------------------------
// K1: Qp = LN1(x_anc) @ W_q.  16 anchors/block, 256 threads.
// ---------------------------------------------------------------------------
__global__ void k_ln1_qproj(const float* __restrict__ x,
                            const float* __restrict__ Wq,
                            const float* __restrict__ g1,
                            const float* __restrict__ b1) {
    __shared__ __align__(16) float xr[16 * 256];
    const int t = threadIdx.x;
    const int a0 = blockIdx.x * 16;

    // Load 16x256 tile, coalesced
    const float4* xg = (const float4*)(x + (size_t)a0 * 256);
#pragma unroll
    for (int i = 0; i < 4; i++) {
        int idx = i * 256 + t;
        ((float4*)xr)[idx] = xg[idx];
    }
    __syncthreads();

    // LayerNorm: warp w handles rows w and w+8
    const int w = t >> 5, lane = t & 31;
#pragma unroll
    for (int rr = 0; rr < 2; rr++) {
        int r = w + rr * 8;
        float s = 0.f, sq = 0.f;
#pragma unroll
        for (int i = 0; i < 8; i++) {
            float v = xr[r * 256 + lane + i * 32];
            s += v; sq += v * v;
        }
#pragma unroll
        for (int o = 16; o > 0; o >>= 1) {
            s  += __shfl_xor_sync(0xffffffff, s, o);
            sq += __shfl_xor_sync(0xffffffff, sq, o);
        }
        float mu = s * (1.f / 256.f);
        float var = sq * (1.f / 256.f) - mu * mu;
        float rstd = rsqrtf(var + 1e-5f);
#pragma unroll
        for (int i = 0; i < 8; i++) {
            int c = lane + i * 32;
            float v = xr[r * 256 + c];
            xr[r * 256 + c] = (v - mu) * rstd * g1[c] + b1[c];
        }
    }
    __syncthreads();

    // GEMM: thread -> 4 cols x 4 anchors
    const int cg = t & 63;    // col group (4 cols)
    const int ag = t >> 6;    // anchor group (4 anchors)
    float acc[4][4];
#pragma unroll
    for (int i = 0; i < 4; i++)
#pragma unroll
        for (int j = 0; j < 4; j++) acc[i][j] = 0.f;

    const float4* W4 = (const float4*)Wq;
    for (int d = 0; d < 256; d++) {
        float4 wv = W4[d * 64 + cg];
#pragma unroll
        for (int i = 0; i < 4; i++) {
            float xv = xr[(ag * 4 + i) * 256 + d];   // warp-uniform broadcast
            acc[i][0] += xv * wv.x; acc[i][1] += xv * wv.y;
            acc[i][2] += xv * wv.z; acc[i][3] += xv * wv.w;
        }
    }
#pragma unroll
    for (int i = 0; i < 4; i++) {
        float4 o = make_float4(acc[i][0], acc[i][1], acc[i][2], acc[i][3]);
        ((float4*)g_q)[(size_t)(a0 + ag * 4 + i) * 64 + cg] = o;
    }
}

// ---------------------------------------------------------------------------
// K2: u[b,h,d] = sum_{d'} Qp[b, h*32+d'] * Wk[d, h*32+d'].  16 anchors/block.
// ---------------------------------------------------------------------------
__global__ void k_uproj(const float* __restrict__ Wk) {
    __shared__ __align__(16) float qsh[16 * 256];
    const int t = threadIdx.x;
    const int a0 = blockIdx.x * 16;

    const float4* qg = (const float4*)g_q + (size_t)a0 * 64;
#pragma unroll
    for (int i = 0; i < 4; i++) {
        int idx = i * 256 + t;
        ((float4*)qsh)[idx] = qg[idx];
    }
    __syncthreads();

    const int d = t;  // output feature index
#pragma unroll
    for (int h = 0; h < 8; h++) {
        float4 wk[8];
        const float4* Wrow = (const float4*)(Wk + (size_t)d * 256 + h * 32);
#pragma unroll
        for (int j = 0; j < 8; j++) wk[j] = Wrow[j];
#pragma unroll
        for (int a = 0; a < 16; a++) {
            const float4* qv = (const float4*)(qsh + a * 256 + h * 32);
            float s = 0.f;
#pragma unroll
            for (int j = 0; j < 8; j++) {
                float4 q = qv[j];
                s += q.x * wk[j].x + q.y * wk[j].y + q.z * wk[j].z + q.w * wk[j].w;
            }
            g_u[(size_t)(a0 + a) * 2048 + h * 256 + d] = s;
        }
    }
}

// ---------------------------------------------------------------------------
// K3: per-anchor attention. scores = Xn @ u^T / sqrt(dk); softmax over k;
//     y[h,:] = attn[h,:] @ Xn.  1 anchor/block, 128 threads. x_nei read ONCE.
// ---------------------------------------------------------------------------
__global__ void k_attn(const float* __restrict__ xnei) {
    __shared__ __align__(16) float us[2048];
    __shared__ __align__(16) float xns[32 * 260];   // padded stride 260
    __shared__ float sc[256];
    __shared__ float attn[256];

    const int t = threadIdx.x;
    const int b = blockIdx.x;

    const float4* ug = (const float4*)g_u + (size_t)b * 512;
#pragma unroll
    for (int i = 0; i < 4; i++) ((float4*)us)[i * 128 + t] = ug[i * 128 + t];

    const float4* xg = (const float4*)xnei + (size_t)b * 2048;
#pragma unroll
    for (int i = 0; i < 16; i++) {
        int vid = i * 128 + t;
        int r = vid >> 6, c = vid & 63;
        ((float4*)(xns + r * 260))[c] = xg[vid];
    }
    __syncthreads();

    // scores (each thread: 2 of the 256 (h,k) pairs)
#pragma unroll
    for (int ii = 0; ii < 2; ii++) {
        int idx = t + ii * 128;
        int h = idx >> 5, k = idx & 31;
        const float4* uq = (const float4*)(us + h * 256);
        const float4* xv = (const float4*)(xns + k * 260);
        float s = 0.f;
#pragma unroll 8
        for (int j = 0; j < 64; j++) {
            float4 a = uq[j], x = xv[j];
            s += a.x * x.x + a.y * x.y + a.z * x.z + a.w * x.w;
        }
        sc[idx] = s * 0.17677669529663687f;   // 1/sqrt(32)
    }
    __syncthreads();

    // softmax per head (warp handles heads w and w+4)
    const int w = t >> 5, lane = t & 31;
    for (int hh = w; hh < 8; hh += 4) {
        float v = sc[hh * 32 + lane];
        float m = v;
#pragma unroll
        for (int o = 16; o > 0; o >>= 1) m = fmaxf(m, __shfl_xor_sync(0xffffffff, m, o));
        float e = expf(v - m);
        float ssum = e;
#pragma unroll
        for (int o = 16; o > 0; o >>= 1) ssum += __shfl_xor_sync(0xffffffff, ssum, o);
        attn[hh * 32 + lane] = e / ssum;
    }
    __syncthreads();

    // y[h,d] = sum_k attn[h,k] * Xn[k,d]
    float4* yg = (float4*)g_y + (size_t)b * 512;
#pragma unroll
    for (int i = 0; i < 4; i++) {
        int vid = i * 128 + t;
        int h = vid >> 6, d4 = vid & 63;
        float4 acc = make_float4(0.f, 0.f, 0.f, 0.f);
#pragma unroll
        for (int k = 0; k < 32; k++) {
            float wgt = attn[h * 32 + k];   // warp-uniform broadcast
            float4 xv = ((const float4*)(xns + k * 260))[d4];
            acc.x += wgt * xv.x; acc.y += wgt * xv.y;
            acc.z += wgt * xv.z; acc.w += wgt * xv.w;
        }
        yg[vid] = acc;
    }
}

// ---------------------------------------------------------------------------
// K4: out[:,h*32+d'] = y_h @ Wv[:,h-slice]; xres = x_anc + out @ Wo;
//     hn = LN2(xres).  4 anchors/block, 256 threads, 40KB STATIC smem.
// ---------------------------------------------------------------------------
__global__ void k_attnout(const float* __restrict__ xanc,
                          const float* __restrict__ Wv,
                          const float* __restrict__ Wo,
                          const float* __restrict__ g2,
                          const float* __restrict__ b2) {
    __shared__ __align__(16) float ysh[2048 * 4];  // [2048][4] (a innermost) 32KB
    __shared__ __align__(16) float osh[256 * 4];   // [256][4]                4KB
    __shared__ __align__(16) float rsh[4 * 256];   // [4][256]                4KB

    const int t = threadIdx.x;
    const int a0 = blockIdx.x * 4;

    // Load y tile transposed (a innermost for vectorized broadcast reads)
#pragma unroll
    for (int a = 0; a < 4; a++) {
        const float4* yg = (const float4*)g_y + (size_t)(a0 + a) * 512;
#pragma unroll
        for (int i = 0; i < 2; i++) {
            int vid = i * 256 + t;
            float4 v = yg[vid];
            int base = vid * 4;
            ysh[(base + 0) * 4 + a] = v.x;
            ysh[(base + 1) * 4 + a] = v.y;
            ysh[(base + 2) * 4 + a] = v.z;
            ysh[(base + 3) * 4 + a] = v.w;
        }
    }
    __syncthreads();

    const int j = t;
    const int h = j >> 5;
    float acc[4];
#pragma unroll
    for (int a = 0; a < 4; a++) acc[a] = 0.f;

    for (int d = 0; d < 256; d++) {
        float wv = Wv[(size_t)d * 256 + j];
        float4 y0 = *(const float4*)(ysh + (h * 256 + d) * 4);  // warp-uniform addr
        acc[0] += y0.x * wv; acc[1] += y0.y * wv;
        acc[2] += y0.z * wv; acc[3] += y0.w * wv;
    }
#pragma unroll
    for (int a = 0; a < 4; a++) osh[j * 4 + a] = acc[a];
    __syncthreads();

    float acc2[4];
#pragma unroll
    for (int a = 0; a < 4; a++) acc2[a] = 0.f;
    for (int i = 0; i < 256; i++) {
        float wo = Wo[(size_t)i * 256 + j];
        float4 o0 = *(const float4*)(osh + i * 4);   // warp-uniform addr
        acc2[0] += o0.x * wo; acc2[1] += o0.y * wo;
        acc2[2] += o0.z * wo; acc2[3] += o0.w * wo;
    }
#pragma unroll
    for (int a = 0; a < 4; a++) {
        float r = xanc[(size_t)(a0 + a) * 256 + j] + acc2[a];
        g_xres[(size_t)(a0 + a) * 256 + j] = r;
        rsh[a * 256 + j] = r;
    }
    __syncthreads();

    // LN2: warps 0-3, one anchor each
    const int w = t >> 5, lane = t & 31;
    if (w < 4) {
        int a = w;
        float s = 0.f, sq = 0.f;
#pragma unroll
        for (int i = 0; i < 8; i++) {
            float v = rsh[a * 256 + lane + i * 32];
            s += v; sq += v * v;
        }
#pragma unroll
        for (int o = 16; o > 0; o >>= 1) {
            s  += __shfl_xor_sync(0xffffffff, s, o);
            sq += __shfl_xor_sync(0xffffffff, sq, o);
        }
        float mu = s * (1.f / 256.f);
        float var = sq * (1.f / 256.f) - mu * mu;
        float rstd = rsqrtf(var + 1e-5f);
#pragma unroll
        for (int i = 0; i < 8; i++) {
            int c = lane + i * 32;
            g_hn[(size_t)(a0 + a) * 256 + c] =
                (rsh[a * 256 + c] - mu) * rstd * g2[c] + b2[c];
        }
    }
}

// ---------------------------------------------------------------------------
// K5/K6: 128x128x8 register-tiled SGEMM, 8x8 per thread, fused epilogue.
// MODE 0: g_ff = gelu(g_hn@W1 + bias)   MODE 1: Cout = g_xres + g_ff@W2 + bias
// A / res / (mode-0 C) are device globals referenced directly — no host-side
// symbol lookups needed in kernel_launch.
// ---------------------------------------------------------------------------
template <int MODE>
__global__ void sgemm_epi(const float* __restrict__ Bm,
                          const float* __restrict__ bias,
                          float* __restrict__ Cout,
                          int M, int N, int Kd) {
    const float* A = (MODE == 0) ? g_hn : g_ff;
    float* C       = (MODE == 0) ? g_ff : Cout;

    __shared__ __align__(16) float As[8][128];
    __shared__ __align__(16) float Bs[8][128];

    const int tid = threadIdx.x;
    const int tx = tid & 15, ty = tid >> 4;
    const int aRow = tid >> 1, aCol = (tid & 1) * 4;
    const int bRow = tid >> 5, bCol = (tid & 31) * 4;

    const float* Ap = A + (size_t)(blockIdx.y * 128 + aRow) * Kd + aCol;
    const float* Bp = Bm + (size_t)bRow * N + blockIdx.x * 128 + bCol;

    float acc[8][8];
#pragma unroll
    for (int i = 0; i < 8; i++)
#pragma unroll
        for (int jj = 0; jj < 8; jj++) acc[i][jj] = 0.f;

    for (int k0 = 0; k0 < Kd; k0 += 8) {
        float4 av = *(const float4*)(Ap + k0);
        float4 bv = *(const float4*)(Bp + (size_t)k0 * N);
        As[aCol + 0][aRow] = av.x;
        As[aCol + 1][aRow] = av.y;
        As[aCol + 2][aRow] = av.z;
        As[aCol + 3][aRow] = av.w;
        *(float4*)(&Bs[bRow][bCol]) = bv;
        __syncthreads();
#pragma unroll
        for (int kk = 0; kk < 8; kk++) {
            float af[8], bf[8];
            *(float4*)(af)     = *(const float4*)(&As[kk][ty * 8]);
            *(float4*)(af + 4) = *(const float4*)(&As[kk][ty * 8 + 4]);
            *(float4*)(bf)     = *(const float4*)(&Bs[kk][tx * 8]);
            *(float4*)(bf + 4) = *(const float4*)(&Bs[kk][tx * 8 + 4]);
#pragma unroll
            for (int i = 0; i < 8; i++)
#pragma unroll
                for (int jj = 0; jj < 8; jj++)
                    acc[i][jj] += af[i] * bf[jj];
        }
        __syncthreads();
    }

#pragma unroll
    for (int i = 0; i < 8; i++) {
        int m = blockIdx.y * 128 + ty * 8 + i;
        int n0 = blockIdx.x * 128 + tx * 8;
#pragma unroll
        for (int half = 0; half < 2; half++) {
            float4 o;
            float* oc = &o.x;
#pragma unroll
            for (int q = 0; q < 4; q++) {
                int n = n0 + half * 4 + q;
                float v = acc[i][half * 4 + q] + bias[n];
                if (MODE == 0) {
                    v = 0.5f * v * (1.0f + erff(v * 0.70710678118654752f));
                } else {
                    v += g_xres[(size_t)m * N + n];
                }
                oc[q] = v;
            }
            *(float4*)(C + (size_t)m * N + n0 + half * 4) = o;
        }
    }
}

// ---------------------------------------------------------------------------
extern "C" void kernel_launch(void* const* d_in, const int* in_sizes, int n_in,
                              void* d_out, int out_size) {
    const float* x_anc = (const float*)d_in[0];
    const float* x_nei = (const float*)d_in[1];
    const float* Wq    = (const float*)d_in[2];
    const float* Wk    = (const float*)d_in[3];
    const float* Wv    = (const float*)d_in[4];
    const float* Wo    = (const float*)d_in[5];
    const float* g1    = (const float*)d_in[6];
    const float* b1    = (const float*)d_in[7];
    const float* g2    = (const float*)d_in[8];
    const float* b2    = (const float*)d_in[9];
    const float* W1    = (const float*)d_in[10];
    const float* bb1   = (const float*)d_in[11];
    const float* W2    = (const float*)d_in[12];
    const float* bb2   = (const float*)d_in[13];
    float* out = (float*)d_out;

    k_ln1_qproj<<<Bn / 16, 256>>>(x_anc, Wq, g1, b1);
    k_uproj<<<Bn / 16, 256>>>(Wk);
    k_attn<<<Bn, 128>>>(x_nei);
    k_attnout<<<Bn / 4, 256>>>(x_anc, Wv, Wo, g2, b2);

    dim3 g5(FFn / 128, Bn / 128);
    sgemm_epi<0><<<g5, 256>>>(W1, bb1, nullptr, Bn, FFn, Dn);
    dim3 g6(Dn / 128, Bn / 128);
    sgemm_epi<1><<<g6, 256>>>(W2, bb2, out, Bn, Dn, FFn);
}

// round 5
// speedup vs baseline: 1.4113x; 1.4113x over previous
#include <cuda_runtime.h>
#include <math.h>
#include <stdint.h>

#define Bn 32768
#define Kn 32
#define Dn 256
#define Hn 8
#define DKn 32
#define FFn 1024

// Scratch (static device globals; allocation-free per harness rules)
__device__ float g_q[Bn * Dn];            // 33.5 MB  Q projection
__device__ float g_u[Bn * Hn * Dn];       // 268 MB   folded-K query vectors
__device__ float g_y[Bn * Hn * Dn];       // 268 MB   attn-weighted neighbor sums
__device__ float g_xres[Bn * Dn];         // 33.5 MB  x + attn_out @ W_o
__device__ float g_hn[Bn * Dn];           // 33.5 MB  LN2(xres)
__device__ float g_ff[Bn * FFn];          // 134 MB   gelu(hn@W1+b1)
__device__ float g_w1t[FFn * Dn];         // 1 MB     W1^T  [N=1024][K=256]
__device__ float g_w2t[Dn * FFn];         // 1 MB     W2^T  [N=256][K=1024]

__device__ __forceinline__ uint32_t tf32r(float x) {
    uint32_t u;
    asm("cvt.rna.tf32.f32 %0, %1;" : "=r"(u) : "f"(x));
    return u;
}

// ---------------------------------------------------------------------------
// K1: Qp = LN1(x_anc) @ W_q.  16 anchors/block, 256 threads.
// ---------------------------------------------------------------------------
__global__ void k_ln1_qproj(const float* __restrict__ x,
                            const float* __restrict__ Wq,
                            const float* __restrict__ g1,
                            const float* __restrict__ b1) {
    __shared__ __align__(16) float xr[16 * 256];
    const int t = threadIdx.x;
    const int a0 = blockIdx.x * 16;

    const float4* xg = (const float4*)(x + (size_t)a0 * 256);
#pragma unroll
    for (int i = 0; i < 4; i++) {
        int idx = i * 256 + t;
        ((float4*)xr)[idx] = xg[idx];
    }
    __syncthreads();

    const int w = t >> 5, lane = t & 31;
#pragma unroll
    for (int rr = 0; rr < 2; rr++) {
        int r = w + rr * 8;
        float s = 0.f, sq = 0.f;
#pragma unroll
        for (int i = 0; i < 8; i++) {
            float v = xr[r * 256 + lane + i * 32];
            s += v; sq += v * v;
        }
#pragma unroll
        for (int o = 16; o > 0; o >>= 1) {
            s  += __shfl_xor_sync(0xffffffff, s, o);
            sq += __shfl_xor_sync(0xffffffff, sq, o);
        }
        float mu = s * (1.f / 256.f);
        float var = sq * (1.f / 256.f) - mu * mu;
        float rstd = rsqrtf(var + 1e-5f);
#pragma unroll
        for (int i = 0; i < 8; i++) {
            int c = lane + i * 32;
            float v = xr[r * 256 + c];
            xr[r * 256 + c] = (v - mu) * rstd * g1[c] + b1[c];
        }
    }
    __syncthreads();

    const int cg = t & 63;
    const int ag = t >> 6;
    float acc[4][4];
#pragma unroll
    for (int i = 0; i < 4; i++)
#pragma unroll
        for (int j = 0; j < 4; j++) acc[i][j] = 0.f;

    const float4* W4 = (const float4*)Wq;
    for (int d = 0; d < 256; d++) {
        float4 wv = W4[d * 64 + cg];
#pragma unroll
        for (int i = 0; i < 4; i++) {
            float xv = xr[(ag * 4 + i) * 256 + d];
            acc[i][0] += xv * wv.x; acc[i][1] += xv * wv.y;
            acc[i][2] += xv * wv.z; acc[i][3] += xv * wv.w;
        }
    }
#pragma unroll
    for (int i = 0; i < 4; i++) {
        float4 o = make_float4(acc[i][0], acc[i][1], acc[i][2], acc[i][3]);
        ((float4*)g_q)[(size_t)(a0 + ag * 4 + i) * 64 + cg] = o;
    }
}

// ---------------------------------------------------------------------------
// K2: u[b,h,d] = sum_{d'} Qp[b, h*32+d'] * Wk[d, h*32+d'].  16 anchors/block.
// ---------------------------------------------------------------------------
__global__ void k_uproj(const float* __restrict__ Wk) {
    __shared__ __align__(16) float qsh[16 * 256];
    const int t = threadIdx.x;
    const int a0 = blockIdx.x * 16;

    const float4* qg = (const float4*)g_q + (size_t)a0 * 64;
#pragma unroll
    for (int i = 0; i < 4; i++) {
        int idx = i * 256 + t;
        ((float4*)qsh)[idx] = qg[idx];
    }
    __syncthreads();

    const int d = t;
#pragma unroll
    for (int h = 0; h < 8; h++) {
        float4 wk[8];
        const float4* Wrow = (const float4*)(Wk + (size_t)d * 256 + h * 32);
#pragma unroll
        for (int j = 0; j < 8; j++) wk[j] = Wrow[j];
#pragma unroll
        for (int a = 0; a < 16; a++) {
            const float4* qv = (const float4*)(qsh + a * 256 + h * 32);
            float s = 0.f;
#pragma unroll
            for (int j = 0; j < 8; j++) {
                float4 q = qv[j];
                s += q.x * wk[j].x + q.y * wk[j].y + q.z * wk[j].z + q.w * wk[j].w;
            }
            g_u[(size_t)(a0 + a) * 2048 + h * 256 + d] = s;
        }
    }
}

// ---------------------------------------------------------------------------
// K3: per-anchor attention. x_nei read ONCE.
// ---------------------------------------------------------------------------
__global__ void k_attn(const float* __restrict__ xnei) {
    __shared__ __align__(16) float us[2048];
    __shared__ __align__(16) float xns[32 * 260];
    __shared__ float sc[256];
    __shared__ float attn[256];

    const int t = threadIdx.x;
    const int b = blockIdx.x;

    const float4* ug = (const float4*)g_u + (size_t)b * 512;
#pragma unroll
    for (int i = 0; i < 4; i++) ((float4*)us)[i * 128 + t] = ug[i * 128 + t];

    const float4* xg = (const float4*)xnei + (size_t)b * 2048;
#pragma unroll
    for (int i = 0; i < 16; i++) {
        int vid = i * 128 + t;
        int r = vid >> 6, c = vid & 63;
        ((float4*)(xns + r * 260))[c] = xg[vid];
    }
    __syncthreads();

#pragma unroll
    for (int ii = 0; ii < 2; ii++) {
        int idx = t + ii * 128;
        int h = idx >> 5, k = idx & 31;
        const float4* uq = (const float4*)(us + h * 256);
        const float4* xv = (const float4*)(xns + k * 260);
        float s = 0.f;
#pragma unroll 8
        for (int j = 0; j < 64; j++) {
            float4 a = uq[j], x = xv[j];
            s += a.x * x.x + a.y * x.y + a.z * x.z + a.w * x.w;
        }
        sc[idx] = s * 0.17677669529663687f;
    }
    __syncthreads();

    const int w = t >> 5, lane = t & 31;
    for (int hh = w; hh < 8; hh += 4) {
        float v = sc[hh * 32 + lane];
        float m = v;
#pragma unroll
        for (int o = 16; o > 0; o >>= 1) m = fmaxf(m, __shfl_xor_sync(0xffffffff, m, o));
        float e = expf(v - m);
        float ssum = e;
#pragma unroll
        for (int o = 16; o > 0; o >>= 1) ssum += __shfl_xor_sync(0xffffffff, ssum, o);
        attn[hh * 32 + lane] = e / ssum;
    }
    __syncthreads();

    float4* yg = (float4*)g_y + (size_t)b * 512;
#pragma unroll
    for (int i = 0; i < 4; i++) {
        int vid = i * 128 + t;
        int h = vid >> 6, d4 = vid & 63;
        float4 acc = make_float4(0.f, 0.f, 0.f, 0.f);
#pragma unroll
        for (int k = 0; k < 32; k++) {
            float wgt = attn[h * 32 + k];
            float4 xv = ((const float4*)(xns + k * 260))[d4];
            acc.x += wgt * xv.x; acc.y += wgt * xv.y;
            acc.z += wgt * xv.z; acc.w += wgt * xv.w;
        }
        yg[vid] = acc;
    }
}

// ---------------------------------------------------------------------------
// K4: attn output proj + residual + LN2.  4 anchors/block, 128 threads,
//     each thread owns 2 adjacent cols (same head) -> LDS bytes/MAC halved.
// ---------------------------------------------------------------------------
__global__ void k_attnout(const float* __restrict__ xanc,
                          const float* __restrict__ Wv,
                          const float* __restrict__ Wo,
                          const float* __restrict__ g2,
                          const float* __restrict__ b2) {
    __shared__ __align__(16) float ysh[2048 * 4];  // [2048][4] 32KB
    __shared__ __align__(16) float osh[256 * 4];   // [256][4]   4KB
    __shared__ __align__(16) float rsh[4 * 256];   // [4][256]   4KB

    const int t = threadIdx.x;           // 0..127
    const int a0 = blockIdx.x * 4;

#pragma unroll
    for (int a = 0; a < 4; a++) {
        const float4* yg = (const float4*)g_y + (size_t)(a0 + a) * 512;
#pragma unroll
        for (int i = 0; i < 4; i++) {
            int vid = i * 128 + t;
            float4 v = yg[vid];
            int base = vid * 4;
            ysh[(base + 0) * 4 + a] = v.x;
            ysh[(base + 1) * 4 + a] = v.y;
            ysh[(base + 2) * 4 + a] = v.z;
            ysh[(base + 3) * 4 + a] = v.w;
        }
    }
    __syncthreads();

    const int j0 = t * 2;
    const int h = j0 >> 5;               // j0 and j0+1 share the same head
    float acc0[4], acc1[4];
#pragma unroll
    for (int a = 0; a < 4; a++) { acc0[a] = 0.f; acc1[a] = 0.f; }

    for (int d = 0; d < 256; d++) {
        float2 wv = *(const float2*)(Wv + (size_t)d * 256 + j0);
        float4 y = *(const float4*)(ysh + (h * 256 + d) * 4);
        acc0[0] += y.x * wv.x; acc0[1] += y.y * wv.x;
        acc0[2] += y.z * wv.x; acc0[3] += y.w * wv.x;
        acc1[0] += y.x * wv.y; acc1[1] += y.y * wv.y;
        acc1[2] += y.z * wv.y; acc1[3] += y.w * wv.y;
    }
#pragma unroll
    for (int a = 0; a < 4; a++) {
        osh[j0 * 4 + a] = acc0[a];
        osh[(j0 + 1) * 4 + a] = acc1[a];
    }
    __syncthreads();

    float ac20[4], ac21[4];
#pragma unroll
    for (int a = 0; a < 4; a++) { ac20[a] = 0.f; ac21[a] = 0.f; }
    for (int i = 0; i < 256; i++) {
        float2 wo = *(const float2*)(Wo + (size_t)i * 256 + j0);
        float4 o = *(const float4*)(osh + i * 4);
        ac20[0] += o.x * wo.x; ac20[1] += o.y * wo.x;
        ac20[2] += o.z * wo.x; ac20[3] += o.w * wo.x;
        ac21[0] += o.x * wo.y; ac21[1] += o.y * wo.y;
        ac21[2] += o.z * wo.y; ac21[3] += o.w * wo.y;
    }
#pragma unroll
    for (int a = 0; a < 4; a++) {
        float2 xv = *(const float2*)(xanc + (size_t)(a0 + a) * 256 + j0);
        float r0 = xv.x + ac20[a];
        float r1 = xv.y + ac21[a];
        *(float2*)(g_xres + (size_t)(a0 + a) * 256 + j0) = make_float2(r0, r1);
        rsh[a * 256 + j0] = r0;
        rsh[a * 256 + j0 + 1] = r1;
    }
    __syncthreads();

    const int w = t >> 5, lane = t & 31;
    {
        int a = w;   // 4 warps, one anchor each
        float s = 0.f, sq = 0.f;
#pragma unroll
        for (int i = 0; i < 8; i++) {
            float v = rsh[a * 256 + lane + i * 32];
            s += v; sq += v * v;
        }
#pragma unroll
        for (int o = 16; o > 0; o >>= 1) {
            s  += __shfl_xor_sync(0xffffffff, s, o);
            sq += __shfl_xor_sync(0xffffffff, sq, o);
        }
        float mu = s * (1.f / 256.f);
        float var = sq * (1.f / 256.f) - mu * mu;
        float rstd = rsqrtf(var + 1e-5f);
#pragma unroll
        for (int i = 0; i < 8; i++) {
            int c = lane + i * 32;
            g_hn[(size_t)(a0 + a) * 256 + c] =
                (rsh[a * 256 + c] - mu) * rstd * g2[c] + b2[c];
        }
    }
}

// ---------------------------------------------------------------------------
// Transpose wrappers writing into device globals
// W1 [256,1024] -> g_w1t [1024,256];  W2 [1024,256] -> g_w2t [256,1024]
// ---------------------------------------------------------------------------
__global__ void k_tr_w1(const float* __restrict__ S) {
    __shared__ float tile[32][33];
    const int bx = blockIdx.x * 32, by = blockIdx.y * 32;
    const int tx = threadIdx.x & 31, ty = threadIdx.x >> 5;
#pragma unroll
    for (int i = 0; i < 32; i += 8)
        tile[ty + i][tx] = S[(size_t)(by + ty + i) * FFn + bx + tx];
    __syncthreads();
#pragma unroll
    for (int i = 0; i < 32; i += 8)
        g_w1t[(size_t)(bx + ty + i) * Dn + by + tx] = tile[tx][ty + i];
}
__global__ void k_tr_w2(const float* __restrict__ S) {
    __shared__ float tile[32][33];
    const int bx = blockIdx.x * 32, by = blockIdx.y * 32;
    const int tx = threadIdx.x & 31, ty = threadIdx.x >> 5;
#pragma unroll
    for (int i = 0; i < 32; i += 8)
        tile[ty + i][tx] = S[(size_t)(by + ty + i) * Dn + bx + tx];
    __syncthreads();
#pragma unroll
    for (int i = 0; i < 32; i += 8)
        g_w2t[(size_t)(bx + ty + i) * FFn + by + tx] = tile[tx][ty + i];
}

// ===========================================================================
// K5/K6: warp-level tf32 MMA GEMM (mma.sync.m16n8k8), 128x128 block tile,
// K streamed in 32-chunks.  8 warps, each warp -> 32x64 sub-tile.
// MODE 0: g_ff = gelu(g_hn @ W1 + b1)      [KD=256,  NTOT=1024]
// MODE 1: Cout = g_xres + g_ff @ W2 + b2   [KD=1024, NTOT=256]
// B operand pre-transposed to [N][K] (g_w1t / g_w2t) == .col layout.
// SMEM stride 36 floats: fragment-load banks (4m+k)%32 injective => no
// conflicts; staging stores are STS.128.
// ===========================================================================
template <int MODE, int KD, int NTOT>
__global__ void __launch_bounds__(256) gemm_mma(const float* __restrict__ bias,
                                                float* __restrict__ Cout) {
    const float* A  = (MODE == 0) ? g_hn  : g_ff;
    const float* Bt = (MODE == 0) ? g_w1t : g_w2t;
    float* C        = (MODE == 0) ? g_ff  : Cout;

    __shared__ __align__(16) uint32_t As[128 * 36];
    __shared__ __align__(16) uint32_t Bs[128 * 36];

    const int t = threadIdx.x;
    const int wid = t >> 5, lane = t & 31;
    const int wm = wid & 3, wn = wid >> 2;        // warp tile: rows 32*wm, cols 64*wn
    const int g = lane >> 2, tq = lane & 3;
    const int m0 = blockIdx.y * 128, n0 = blockIdx.x * 128;

    float acc[2][8][4];
#pragma unroll
    for (int mt = 0; mt < 2; mt++)
#pragma unroll
        for (int nt = 0; nt < 8; nt++)
#pragma unroll
            for (int e = 0; e < 4; e++) acc[mt][nt][e] = 0.f;

    for (int k0 = 0; k0 < KD; k0 += 32) {
        // stage 128x32 A and B tiles (converted to tf32)
#pragma unroll
        for (int it = 0; it < 4; it++) {
            int v = it * 256 + t;
            int r = v >> 3, kg = v & 7;
            float4 av = *(const float4*)(A  + (size_t)(m0 + r) * KD + k0 + kg * 4);
            float4 bv = *(const float4*)(Bt + (size_t)(n0 + r) * KD + k0 + kg * 4);
            uint4 ua, ub;
            ua.x = tf32r(av.x); ua.y = tf32r(av.y);
            ua.z = tf32r(av.z); ua.w = tf32r(av.w);
            ub.x = tf32r(bv.x); ub.y = tf32r(bv.y);
            ub.z = tf32r(bv.z); ub.w = tf32r(bv.w);
            *(uint4*)&As[r * 36 + kg * 4] = ua;
            *(uint4*)&Bs[r * 36 + kg * 4] = ub;
        }
        __syncthreads();

#pragma unroll
        for (int ks = 0; ks < 4; ks++) {
            const int cc = ks * 8 + tq;
            uint32_t a[2][4];
#pragma unroll
            for (int mt = 0; mt < 2; mt++) {
                int row = wm * 32 + mt * 16 + g;
                a[mt][0] = As[row * 36 + cc];
                a[mt][1] = As[(row + 8) * 36 + cc];
                a[mt][2] = As[row * 36 + cc + 4];
                a[mt][3] = As[(row + 8) * 36 + cc + 4];
            }
#pragma unroll
            for (int nt = 0; nt < 8; nt++) {
                int col = wn * 64 + nt * 8 + g;
                uint32_t b0 = Bs[col * 36 + cc];
                uint32_t b1 = Bs[col * 36 + cc + 4];
#pragma unroll
                for (int mt = 0; mt < 2; mt++) {
                    asm volatile(
                        "mma.sync.aligned.m16n8k8.row.col.f32.tf32.tf32.f32 "
                        "{%0,%1,%2,%3}, {%4,%5,%6,%7}, {%8,%9}, {%0,%1,%2,%3};"
                        : "+f"(acc[mt][nt][0]), "+f"(acc[mt][nt][1]),
                          "+f"(acc[mt][nt][2]), "+f"(acc[mt][nt][3])
                        : "r"(a[mt][0]), "r"(a[mt][1]), "r"(a[mt][2]), "r"(a[mt][3]),
                          "r"(b0), "r"(b1));
                }
            }
        }
        __syncthreads();
    }

    // Epilogue: c0,c1 -> (row, col..col+1), c2,c3 -> (row+8, ...)
#pragma unroll
    for (int mt = 0; mt < 2; mt++) {
        int row0 = m0 + wm * 32 + mt * 16 + g;
#pragma unroll
        for (int nt = 0; nt < 8; nt++) {
            int col = n0 + wn * 64 + nt * 8 + tq * 2;
            float bi0 = bias[col], bi1 = bias[col + 1];
#pragma unroll
            for (int half = 0; half < 2; half++) {
                int m = row0 + half * 8;
                float v0 = acc[mt][nt][half * 2 + 0] + bi0;
                float v1 = acc[mt][nt][half * 2 + 1] + bi1;
                if (MODE == 0) {
                    v0 = 0.5f * v0 * (1.0f + erff(v0 * 0.70710678118654752f));
                    v1 = 0.5f * v1 * (1.0f + erff(v1 * 0.70710678118654752f));
                } else {
                    float2 xv = *(const float2*)(g_xres + (size_t)m * 256 + col);
                    v0 += xv.x; v1 += xv.y;
                }
                *(float2*)(C + (size_t)m * NTOT + col) = make_float2(v0, v1);
            }
        }
    }
}

// ---------------------------------------------------------------------------
extern "C" void kernel_launch(void* const* d_in, const int* in_sizes, int n_in,
                              void* d_out, int out_size) {
    const float* x_anc = (const float*)d_in[0];
    const float* x_nei = (const float*)d_in[1];
    const float* Wq    = (const float*)d_in[2];
    const float* Wk    = (const float*)d_in[3];
    const float* Wv    = (const float*)d_in[4];
    const float* Wo    = (const float*)d_in[5];
    const float* g1    = (const float*)d_in[6];
    const float* b1    = (const float*)d_in[7];
    const float* g2    = (const float*)d_in[8];
    const float* b2    = (const float*)d_in[9];
    const float* W1    = (const float*)d_in[10];
    const float* bb1   = (const float*)d_in[11];
    const float* W2    = (const float*)d_in[12];
    const float* bb2   = (const float*)d_in[13];
    float* out = (float*)d_out;

    k_tr_w1<<<dim3(FFn / 32, Dn / 32), 256>>>(W1);
    k_tr_w2<<<dim3(Dn / 32, FFn / 32), 256>>>(W2);

    k_ln1_qproj<<<Bn / 16, 256>>>(x_anc, Wq, g1, b1);
    k_uproj<<<Bn / 16, 256>>>(Wk);
    k_attn<<<Bn, 128>>>(x_nei);
    k_attnout<<<Bn / 4, 128>>>(x_anc, Wv, Wo, g2, b2);

    gemm_mma<0, Dn, FFn><<<dim3(FFn / 128, Bn / 128), 256>>>(bb1, nullptr);
    gemm_mma<1, FFn, Dn><<<dim3(Dn / 128, Bn / 128), 256>>>(bb2, out);
}

// round 6
// speedup vs baseline: 3.2852x; 2.3278x over previous
#include <cuda_runtime.h>
#include <math.h>
#include <stdint.h>

#define Bn 32768
#define Kn 32
#define Dn 256
#define Hn 8
#define DKn 32
#define FFn 1024

// Scratch (static device globals; allocation-free per harness rules)
__device__ float g_ln[Bn * Dn];           // LN1(x_anc)
__device__ float g_q[Bn * Dn];            // Q projection
__device__ float g_u[Bn * Hn * Dn];       // folded-K query vectors [B][h*256+d]
__device__ float g_y[Bn * Hn * Dn];       // attn-weighted neighbor sums
__device__ float g_o[Bn * Dn];            // per-head V-projected attn out
__device__ float g_xres[Bn * Dn];         // x + attn_out @ W_o
__device__ float g_hn[Bn * Dn];           // LN2(xres)
__device__ float g_ff[Bn * FFn];          // gelu(hn@W1+b1)
__device__ float g_wqt[Dn * Dn];          // Wq^T
__device__ float g_wvt[Dn * Dn];          // Wv^T
__device__ float g_wot[Dn * Dn];          // Wo^T
__device__ float g_w1t[FFn * Dn];         // W1^T  [1024][256]
__device__ float g_w2t[Dn * FFn];         // W2^T  [256][1024]

__device__ __forceinline__ uint32_t tf32r(float x) {
    uint32_t u;
    asm("cvt.rna.tf32.f32 %0, %1;" : "=r"(u) : "f"(x));
    return u;
}

// ---------------------------------------------------------------------------
// Transposes: 256x256 (Wq/Wv/Wo via SEL) + W1 + W2
// ---------------------------------------------------------------------------
template <int SEL>
__global__ void k_tr256(const float* __restrict__ S) {
    float* Dst = (SEL == 0) ? g_wqt : (SEL == 1) ? g_wvt : g_wot;
    __shared__ float tile[32][33];
    const int bx = blockIdx.x * 32, by = blockIdx.y * 32;
    const int tx = threadIdx.x & 31, ty = threadIdx.x >> 5;
#pragma unroll
    for (int i = 0; i < 32; i += 8)
        tile[ty + i][tx] = S[(size_t)(by + ty + i) * 256 + bx + tx];
    __syncthreads();
#pragma unroll
    for (int i = 0; i < 32; i += 8)
        Dst[(size_t)(bx + ty + i) * 256 + by + tx] = tile[tx][ty + i];
}
__global__ void k_tr_w1(const float* __restrict__ S) {
    __shared__ float tile[32][33];
    const int bx = blockIdx.x * 32, by = blockIdx.y * 32;
    const int tx = threadIdx.x & 31, ty = threadIdx.x >> 5;
#pragma unroll
    for (int i = 0; i < 32; i += 8)
        tile[ty + i][tx] = S[(size_t)(by + ty + i) * FFn + bx + tx];
    __syncthreads();
#pragma unroll
    for (int i = 0; i < 32; i += 8)
        g_w1t[(size_t)(bx + ty + i) * Dn + by + tx] = tile[tx][ty + i];
}
__global__ void k_tr_w2(const float* __restrict__ S) {
    __shared__ float tile[32][33];
    const int bx = blockIdx.x * 32, by = blockIdx.y * 32;
    const int tx = threadIdx.x & 31, ty = threadIdx.x >> 5;
#pragma unroll
    for (int i = 0; i < 32; i += 8)
        tile[ty + i][tx] = S[(size_t)(by + ty + i) * Dn + bx + tx];
    __syncthreads();
#pragma unroll
    for (int i = 0; i < 32; i += 8)
        g_w2t[(size_t)(bx + ty + i) * FFn + by + tx] = tile[tx][ty + i];
}

// ---------------------------------------------------------------------------
// LayerNorm: SEL 0: g_ln = LN(srcArg)   SEL 1: g_hn = LN(g_xres)
// 8 rows/block (1 warp per row), 256 threads.
// ---------------------------------------------------------------------------
template <int SEL>
__global__ void k_ln(const float* __restrict__ srcArg,
                     const float* __restrict__ gam,
                     const float* __restrict__ bet) {
    const float* src = (SEL == 0) ? srcArg : g_xres;
    float* dst       = (SEL == 0) ? g_ln   : g_hn;
    const int w = threadIdx.x >> 5, lane = threadIdx.x & 31;
    const int row = blockIdx.x * 8 + w;

    const float4* s4 = (const float4*)(src + (size_t)row * 256);
    float4 v0 = s4[lane], v1 = s4[lane + 32];
    float s  = v0.x + v0.y + v0.z + v0.w + v1.x + v1.y + v1.z + v1.w;
    float sq = v0.x*v0.x + v0.y*v0.y + v0.z*v0.z + v0.w*v0.w
             + v1.x*v1.x + v1.y*v1.y + v1.z*v1.z + v1.w*v1.w;
#pragma unroll
    for (int o = 16; o > 0; o >>= 1) {
        s  += __shfl_xor_sync(0xffffffff, s, o);
        sq += __shfl_xor_sync(0xffffffff, sq, o);
    }
    float mu = s * (1.f / 256.f);
    float var = sq * (1.f / 256.f) - mu * mu;
    float rstd = rsqrtf(var + 1e-5f);

    float4 ga = ((const float4*)gam)[lane], gb = ((const float4*)gam)[lane + 32];
    float4 ba = ((const float4*)bet)[lane], bb = ((const float4*)bet)[lane + 32];
    float4 o0, o1;
    o0.x = (v0.x - mu) * rstd * ga.x + ba.x;
    o0.y = (v0.y - mu) * rstd * ga.y + ba.y;
    o0.z = (v0.z - mu) * rstd * ga.z + ba.z;
    o0.w = (v0.w - mu) * rstd * ga.w + ba.w;
    o1.x = (v1.x - mu) * rstd * gb.x + bb.x;
    o1.y = (v1.y - mu) * rstd * gb.y + bb.y;
    o1.z = (v1.z - mu) * rstd * gb.z + bb.z;
    o1.w = (v1.w - mu) * rstd * gb.w + bb.w;
    float4* d4 = (float4*)(dst + (size_t)row * 256);
    d4[lane] = o0; d4[lane + 32] = o1;
}

// ---------------------------------------------------------------------------
// K3: per-anchor attention. x_nei read ONCE. (unchanged, verified)
// ---------------------------------------------------------------------------
__global__ void k_attn(const float* __restrict__ xnei) {
    __shared__ __align__(16) float us[2048];
    __shared__ __align__(16) float xns[32 * 260];
    __shared__ float sc[256];
    __shared__ float attn[256];

    const int t = threadIdx.x;
    const int b = blockIdx.x;

    const float4* ug = (const float4*)g_u + (size_t)b * 512;
#pragma unroll
    for (int i = 0; i < 4; i++) ((float4*)us)[i * 128 + t] = ug[i * 128 + t];

    const float4* xg = (const float4*)xnei + (size_t)b * 2048;
#pragma unroll
    for (int i = 0; i < 16; i++) {
        int vid = i * 128 + t;
        int r = vid >> 6, c = vid & 63;
        ((float4*)(xns + r * 260))[c] = xg[vid];
    }
    __syncthreads();

#pragma unroll
    for (int ii = 0; ii < 2; ii++) {
        int idx = t + ii * 128;
        int h = idx >> 5, k = idx & 31;
        const float4* uq = (const float4*)(us + h * 256);
        const float4* xv = (const float4*)(xns + k * 260);
        float s = 0.f;
#pragma unroll 8
        for (int j = 0; j < 64; j++) {
            float4 a = uq[j], x = xv[j];
            s += a.x * x.x + a.y * x.y + a.z * x.z + a.w * x.w;
        }
        sc[idx] = s * 0.17677669529663687f;
    }
    __syncthreads();

    const int w = t >> 5, lane = t & 31;
    for (int hh = w; hh < 8; hh += 4) {
        float v = sc[hh * 32 + lane];
        float m = v;
#pragma unroll
        for (int o = 16; o > 0; o >>= 1) m = fmaxf(m, __shfl_xor_sync(0xffffffff, m, o));
        float e = expf(v - m);
        float ssum = e;
#pragma unroll
        for (int o = 16; o > 0; o >>= 1) ssum += __shfl_xor_sync(0xffffffff, ssum, o);
        attn[hh * 32 + lane] = e / ssum;
    }
    __syncthreads();

    float4* yg = (float4*)g_y + (size_t)b * 512;
#pragma unroll
    for (int i = 0; i < 4; i++) {
        int vid = i * 128 + t;
        int h = vid >> 6, d4 = vid & 63;
        float4 acc = make_float4(0.f, 0.f, 0.f, 0.f);
#pragma unroll
        for (int k = 0; k < 32; k++) {
            float wgt = attn[h * 32 + k];
            float4 xv = ((const float4*)(xns + k * 260))[d4];
            acc.x += wgt * xv.x; acc.y += wgt * xv.y;
            acc.z += wgt * xv.z; acc.w += wgt * xv.w;
        }
        yg[vid] = acc;
    }
}

// ===========================================================================
// Unified tf32 MMA GEMM (mma.sync.m16n8k8).  M tile = 128 rows, 256 threads.
// ID 0 Qproj:  g_q   = g_ln @ Wq                (BN=128, KD=256)
// ID 1 uproj:  g_u_h = g_q[:,h32] @ Wk_h^T      (BN=128, KD=32, bz=head)
// ID 2 vproj:  g_o_h = g_y[:,h256] @ Wv_h^T     (BN=32,  KD=256, bx=head)
// ID 3 oproj:  g_xres = x_anc + g_o @ Wo        (BN=128, KD=256)
// ID 4 ffn1:   g_ff  = gelu(g_hn @ W1 + b1)     (BN=128, KD=256)
// ID 5 ffn2:   out   = g_xres + g_ff @ W2 + b2  (BN=128, KD=1024)
// ===========================================================================
template <int ID>
__global__ void __launch_bounds__(256) gemm_k(const float* __restrict__ p0,
                                              float* __restrict__ pout) {
    constexpr int BN  = (ID == 2) ? 32 : 128;
    constexpr int KD  = (ID == 1) ? 32 : (ID == 5 ? 1024 : 256);
    constexpr int LDB = (ID == 1) ? 256 : KD;
    constexpr int NT  = (BN == 128) ? 8 : 2;
    constexpr int WNW = (BN == 128) ? 64 : 16;

    const int t = threadIdx.x;
    const int wid = t >> 5, lane = t & 31;
    const int g = lane >> 2, tq = lane & 3;
    const int wm = wid & 3, wn = wid >> 2;
    const int m0 = blockIdx.y * 128;

    const float* A;  int lda, acol;
    const float* Bt;
    float* C;        int ldc, ccol;
    const float* bias = nullptr;
    const float* res  = nullptr;

    if constexpr (ID == 0) {
        A = g_ln; lda = 256; acol = 0;
        Bt = g_wqt + (size_t)blockIdx.x * 128 * LDB;
        C = g_q; ldc = 256; ccol = blockIdx.x * 128;
    } else if constexpr (ID == 1) {
        const int h = blockIdx.z;
        A = g_q; lda = 256; acol = h * 32;
        Bt = p0 + h * 32 + (size_t)blockIdx.x * 128 * LDB;
        C = g_u; ldc = 2048; ccol = h * 256 + blockIdx.x * 128;
    } else if constexpr (ID == 2) {
        const int h = blockIdx.x;
        A = g_y; lda = 2048; acol = h * 256;
        Bt = g_wvt + (size_t)h * 32 * LDB;
        C = g_o; ldc = 256; ccol = h * 32;
    } else if constexpr (ID == 3) {
        A = g_o; lda = 256; acol = 0;
        Bt = g_wot + (size_t)blockIdx.x * 128 * LDB;
        C = g_xres; ldc = 256; ccol = blockIdx.x * 128;
        res = p0;                               // x_anc
    } else if constexpr (ID == 4) {
        A = g_hn; lda = 256; acol = 0;
        Bt = g_w1t + (size_t)blockIdx.x * 128 * LDB;
        C = g_ff; ldc = 1024; ccol = blockIdx.x * 128;
        bias = p0;
    } else {
        A = g_ff; lda = 1024; acol = 0;
        Bt = g_w2t + (size_t)blockIdx.x * 128 * LDB;
        C = pout; ldc = 256; ccol = blockIdx.x * 128;
        bias = p0; res = g_xres;
    }

    __shared__ __align__(16) uint32_t As[128 * 36];
    __shared__ __align__(16) uint32_t Bs[BN * 36];

    float acc[2][NT][4];
#pragma unroll
    for (int mt = 0; mt < 2; mt++)
#pragma unroll
        for (int nt = 0; nt < NT; nt++)
#pragma unroll
            for (int e = 0; e < 4; e++) acc[mt][nt][e] = 0.f;

    for (int k0 = 0; k0 < KD; k0 += 32) {
        // stage A 128x32
#pragma unroll
        for (int it = 0; it < 4; it++) {
            int v = it * 256 + t;
            int r = v >> 3, kg = v & 7;
            float4 av = *(const float4*)(A + (size_t)(m0 + r) * lda + acol + k0 + kg * 4);
            uint4 ua;
            ua.x = tf32r(av.x); ua.y = tf32r(av.y);
            ua.z = tf32r(av.z); ua.w = tf32r(av.w);
            *(uint4*)&As[r * 36 + kg * 4] = ua;
        }
        // stage B BNx32
#pragma unroll
        for (int it = 0; it < BN / 32; it++) {
            int v = it * 256 + t;
            int r = v >> 3, kg = v & 7;
            float4 bv = *(const float4*)(Bt + (size_t)r * LDB + k0 + kg * 4);
            uint4 ub;
            ub.x = tf32r(bv.x); ub.y = tf32r(bv.y);
            ub.z = tf32r(bv.z); ub.w = tf32r(bv.w);
            *(uint4*)&Bs[r * 36 + kg * 4] = ub;
        }
        __syncthreads();

#pragma unroll
        for (int ks = 0; ks < 4; ks++) {
            const int cc = ks * 8 + tq;
            uint32_t a[2][4];
#pragma unroll
            for (int mt = 0; mt < 2; mt++) {
                int row = wm * 32 + mt * 16 + g;
                a[mt][0] = As[row * 36 + cc];
                a[mt][1] = As[(row + 8) * 36 + cc];
                a[mt][2] = As[row * 36 + cc + 4];
                a[mt][3] = As[(row + 8) * 36 + cc + 4];
            }
#pragma unroll
            for (int nt = 0; nt < NT; nt++) {
                int col = wn * WNW + nt * 8 + g;
                uint32_t b0 = Bs[col * 36 + cc];
                uint32_t b1 = Bs[col * 36 + cc + 4];
#pragma unroll
                for (int mt = 0; mt < 2; mt++) {
                    asm volatile(
                        "mma.sync.aligned.m16n8k8.row.col.f32.tf32.tf32.f32 "
                        "{%0,%1,%2,%3}, {%4,%5,%6,%7}, {%8,%9}, {%0,%1,%2,%3};"
                        : "+f"(acc[mt][nt][0]), "+f"(acc[mt][nt][1]),
                          "+f"(acc[mt][nt][2]), "+f"(acc[mt][nt][3])
                        : "r"(a[mt][0]), "r"(a[mt][1]), "r"(a[mt][2]), "r"(a[mt][3]),
                          "r"(b0), "r"(b1));
                }
            }
        }
        __syncthreads();
    }

    // Epilogue
#pragma unroll
    for (int mt = 0; mt < 2; mt++) {
        int row0 = m0 + wm * 32 + mt * 16 + g;
#pragma unroll
        for (int nt = 0; nt < NT; nt++) {
            int col = ccol + wn * WNW + nt * 8 + tq * 2;
            float bi0 = 0.f, bi1 = 0.f;
            if (bias) { bi0 = bias[col]; bi1 = bias[col + 1]; }
#pragma unroll
            for (int half = 0; half < 2; half++) {
                int m = row0 + half * 8;
                float v0 = acc[mt][nt][half * 2 + 0] + bi0;
                float v1 = acc[mt][nt][half * 2 + 1] + bi1;
                if constexpr (ID == 4) {
                    v0 = 0.5f * v0 * (1.0f + erff(v0 * 0.70710678118654752f));
                    v1 = 0.5f * v1 * (1.0f + erff(v1 * 0.70710678118654752f));
                }
                if constexpr (ID == 3 || ID == 5) {
                    float2 xv = *(const float2*)(res + (size_t)m * 256 + col);
                    v0 += xv.x; v1 += xv.y;
                }
                *(float2*)(C + (size_t)m * ldc + col) = make_float2(v0, v1);
            }
        }
    }
}

// ---------------------------------------------------------------------------
extern "C" void kernel_launch(void* const* d_in, const int* in_sizes, int n_in,
                              void* d_out, int out_size) {
    const float* x_anc = (const float*)d_in[0];
    const float* x_nei = (const float*)d_in[1];
    const float* Wq    = (const float*)d_in[2];
    const float* Wk    = (const float*)d_in[3];
    const float* Wv    = (const float*)d_in[4];
    const float* Wo    = (const float*)d_in[5];
    const float* g1    = (const float*)d_in[6];
    const float* b1    = (const float*)d_in[7];
    const float* g2    = (const float*)d_in[8];
    const float* b2    = (const float*)d_in[9];
    const float* W1    = (const float*)d_in[10];
    const float* bb1   = (const float*)d_in[11];
    const float* W2    = (const float*)d_in[12];
    const float* bb2   = (const float*)d_in[13];
    float* out = (float*)d_out;

    k_tr256<0><<<dim3(8, 8), 256>>>(Wq);
    k_tr256<1><<<dim3(8, 8), 256>>>(Wv);
    k_tr256<2><<<dim3(8, 8), 256>>>(Wo);
    k_tr_w1<<<dim3(FFn / 32, Dn / 32), 256>>>(W1);
    k_tr_w2<<<dim3(Dn / 32, FFn / 32), 256>>>(W2);

    k_ln<0><<<Bn / 8, 256>>>(x_anc, g1, b1);
    gemm_k<0><<<dim3(2, Bn / 128), 256>>>(nullptr, nullptr);       // Qproj
    gemm_k<1><<<dim3(2, Bn / 128, Hn), 256>>>(Wk, nullptr);        // uproj
    k_attn<<<Bn, 128>>>(x_nei);
    gemm_k<2><<<dim3(Hn, Bn / 128), 256>>>(nullptr, nullptr);      // vproj
    gemm_k<3><<<dim3(2, Bn / 128), 256>>>(x_anc, nullptr);         // oproj+res
    k_ln<1><<<Bn / 8, 256>>>(nullptr, g2, b2);
    gemm_k<4><<<dim3(8, Bn / 128), 256>>>(bb1, nullptr);           // ffn1
    gemm_k<5><<<dim3(2, Bn / 128), 256>>>(bb2, out);               // ffn2
}